// round 2
// baseline (speedup 1.0000x reference)
#include <cuda_runtime.h>
#include <cuda_bf16.h>
#include <cstdint>

// ---------------- problem constants ----------------
#define S_LEN 2048
#define DIM   4096
#define NH    32
#define NKV   8
#define HD    128
#define KVDIM (NKV * HD)        // 1024
#define ATT_SCALE 0.08838834764831845f  // 128^-0.5

// ---------------- scratch (no allocations allowed) ----------------
__device__ float g_Q[S_LEN * DIM];     // 32 MB
__device__ float g_K[S_LEN * KVDIM];   //  8 MB
__device__ float g_V[S_LEN * KVDIM];   //  8 MB
__device__ float g_A[S_LEN * DIM];     // 32 MB (attention output, pre-Wo)

// ---------------- SGEMM: C[M,N] = A[M,K] @ B[K,N], all row-major ----------------
// BM=BN=128, BK=8, 256 threads, 8x8 microtile per thread, warp tile 32x64.
#define GBM 128
#define GBN 128
#define GBK 8

__global__ __launch_bounds__(256, 2) void sgemm128(
    const float* __restrict__ A, const float* __restrict__ B,
    float* __restrict__ C, int M, int N, int K)
{
    __shared__ float As[GBK][GBM];      // transposed A tile
    __shared__ float Bs[GBK][GBN];

    const int tid = threadIdx.x;
    const int rowBase = blockIdx.y * GBM;
    const int colBase = blockIdx.x * GBN;

    // warp tiling: 4 warp-rows x 2 warp-cols; lane: 4x8
    const int warp = tid >> 5;
    const int lane = tid & 31;
    const int warpRow = warp >> 1;          // 0..3
    const int warpCol = warp & 1;           // 0..1
    const int lrow = lane >> 3;             // 0..3
    const int lcol = lane & 7;              // 0..7
    const int rowOff = warpRow * 32 + lrow * 8;
    const int colOff = warpCol * 64 + lcol * 8;

    // load mapping (one float4 of A and one float4 of B per thread per k-step)
    const int aRow  = tid >> 1;             // 0..127
    const int aCol4 = (tid & 1) * 4;        // 0 or 4
    const int bRow  = tid >> 5;             // 0..7
    const int bCol4 = (tid & 31) * 4;       // 0..124

    const float* Aptr = A + (size_t)(rowBase + aRow) * K + aCol4;
    const float* Bptr = B + (size_t)bRow * N + colBase + bCol4;

    float acc[8][8];
    #pragma unroll
    for (int i = 0; i < 8; i++)
        #pragma unroll
        for (int j = 0; j < 8; j++) acc[i][j] = 0.f;

    for (int k0 = 0; k0 < K; k0 += GBK) {
        float4 av = *(const float4*)(Aptr + k0);
        float4 bv = *(const float4*)(Bptr + (size_t)k0 * N);
        As[aCol4 + 0][aRow] = av.x;
        As[aCol4 + 1][aRow] = av.y;
        As[aCol4 + 2][aRow] = av.z;
        As[aCol4 + 3][aRow] = av.w;
        *(float4*)&Bs[bRow][bCol4] = bv;
        __syncthreads();

        #pragma unroll
        for (int kk = 0; kk < GBK; kk++) {
            float ra[8], rb[8];
            *(float4*)&ra[0] = *(const float4*)&As[kk][rowOff];
            *(float4*)&ra[4] = *(const float4*)&As[kk][rowOff + 4];
            *(float4*)&rb[0] = *(const float4*)&Bs[kk][colOff];
            *(float4*)&rb[4] = *(const float4*)&Bs[kk][colOff + 4];
            #pragma unroll
            for (int i = 0; i < 8; i++)
                #pragma unroll
                for (int j = 0; j < 8; j++)
                    acc[i][j] += ra[i] * rb[j];
        }
        __syncthreads();
    }

    #pragma unroll
    for (int i = 0; i < 8; i++) {
        float* cp = C + (size_t)(rowBase + rowOff + i) * N + colBase + colOff;
        *(float4*)cp       = make_float4(acc[i][0], acc[i][1], acc[i][2], acc[i][3]);
        *(float4*)(cp + 4) = make_float4(acc[i][4], acc[i][5], acc[i][6], acc[i][7]);
    }
}

// ---------------- RoPE (interleaved pairs, matches reference) ----------------
__global__ void rope_kernel(float* __restrict__ t,
                            const float* __restrict__ cosb,
                            const float* __restrict__ sinb,
                            int nheads)
{
    int idx = blockIdx.x * blockDim.x + threadIdx.x;
    int total = S_LEN * nheads * (HD / 2);
    if (idx >= total) return;
    int i = idx & 63;                 // pair index 0..63
    int h = (idx >> 6) % nheads;
    int s = idx / (64 * nheads);
    float c  = cosb[s * 64 + i];
    float sn = sinb[s * 64 + i];
    float* p = t + (size_t)s * (nheads * HD) + h * HD + 2 * i;
    float t0 = p[0], t1 = p[1];
    p[0] = t0 * c - t1 * sn;
    p[1] = t0 * sn + t1 * c;
}

// ---------------- Flash-style causal attention ----------------
// grid: (S/BQ, NH). 256 threads. BQ=BKV=64. fp32, online softmax.
#define BQ  64
#define BKV 64
#define KS_STRIDE 129          // padded K-tile row stride (conflict-free scalar reads)
#define SS_STRIDE 65

// smem floats: Qs 64*128 + Ks 64*129 + Vs 64*128 + Ss 64*65 + 3*64
#define ATTN_SMEM_FLOATS (64*128 + 64*KS_STRIDE + 64*128 + 64*SS_STRIDE + 192)
#define ATTN_SMEM_BYTES  (ATTN_SMEM_FLOATS * 4)

__global__ __launch_bounds__(256, 2) void attn_kernel(
    const float* __restrict__ Q, const float* __restrict__ K,
    const float* __restrict__ V, float* __restrict__ O)
{
    extern __shared__ float sm[];
    float* Qs = sm;                        // [64][128]
    float* Ks = Qs + 64 * 128;             // [64][129]
    float* Vs = Ks + 64 * KS_STRIDE;       // [64][128]
    float* Ss = Vs + 64 * 128;             // [64][65]
    float* rowM = Ss + 64 * SS_STRIDE;
    float* rowL = rowM + 64;
    float* rowScale = rowL + 64;

    const int tid  = threadIdx.x;
    const int qt   = blockIdx.x;
    const int head = blockIdx.y;
    const int kvh  = head >> 2;            // REPEATS = 4
    const int qBase = qt * BQ;

    // load Q tile (coalesced float4)
    for (int i = tid; i < BQ * (HD / 4); i += 256) {
        int r = i >> 5, c4 = (i & 31) << 2;
        *(float4*)&Qs[r * HD + c4] =
            *(const float4*)(Q + (size_t)(qBase + r) * DIM + head * HD + c4);
    }
    if (tid < 64) { rowM[tid] = -1e30f; rowL[tid] = 0.f; }

    float acc[32];
    #pragma unroll
    for (int i = 0; i < 32; i++) acc[i] = 0.f;

    // PV / output mapping: thread owns row r_pv, cols {4*cg + 16*c + j}
    const int r_pv = tid >> 2;     // 0..63
    const int cg   = tid & 3;      // 0..3

    // score mapping: rows ty*4+i (i<4), cols tx+16*j (j<4)
    const int ty = tid >> 4;       // 0..15
    const int tx = tid & 15;       // 0..15

    const int nkb = qt + 1;        // causal: only blocks with kvStart <= qEnd
    for (int kb = 0; kb < nkb; kb++) {
        const int kvStart = kb * BKV;
        __syncthreads();   // previous iter's Ss/Vs consumers done; Qs visible (iter 0)

        // load K/V tiles
        for (int i = tid; i < BKV * (HD / 4); i += 256) {
            int r = i >> 5, c4 = (i & 31) << 2;
            float4 k4 = *(const float4*)(K + (size_t)(kvStart + r) * KVDIM + kvh * HD + c4);
            Ks[r * KS_STRIDE + c4 + 0] = k4.x;
            Ks[r * KS_STRIDE + c4 + 1] = k4.y;
            Ks[r * KS_STRIDE + c4 + 2] = k4.z;
            Ks[r * KS_STRIDE + c4 + 3] = k4.w;
            *(float4*)&Vs[r * HD + c4] =
                *(const float4*)(V + (size_t)(kvStart + r) * KVDIM + kvh * HD + c4);
        }
        __syncthreads();

        // scores: 4x4 per thread
        float s4[4][4];
        #pragma unroll
        for (int i = 0; i < 4; i++)
            #pragma unroll
            for (int j = 0; j < 4; j++) s4[i][j] = 0.f;

        for (int d = 0; d < HD; d++) {
            float qv[4], kv[4];
            #pragma unroll
            for (int i = 0; i < 4; i++) qv[i] = Qs[(ty * 4 + i) * HD + d];
            #pragma unroll
            for (int j = 0; j < 4; j++) kv[j] = Ks[(tx + 16 * j) * KS_STRIDE + d];
            #pragma unroll
            for (int i = 0; i < 4; i++)
                #pragma unroll
                for (int j = 0; j < 4; j++)
                    s4[i][j] += qv[i] * kv[j];
        }
        #pragma unroll
        for (int i = 0; i < 4; i++) {
            int qpos = qBase + ty * 4 + i;
            #pragma unroll
            for (int j = 0; j < 4; j++) {
                int kpos = kvStart + tx + 16 * j;
                float v = s4[i][j] * ATT_SCALE;
                if (kpos > qpos) v = -1e9f;
                Ss[(ty * 4 + i) * SS_STRIDE + tx + 16 * j] = v;
            }
        }
        __syncthreads();

        // online softmax row update (one thread per row)
        if (tid < 64) {
            float m = rowM[tid];
            float mx = m;
            #pragma unroll 8
            for (int j = 0; j < BKV; j++) mx = fmaxf(mx, Ss[tid * SS_STRIDE + j]);
            float sc = __expf(m - mx);
            float l = rowL[tid] * sc;
            #pragma unroll 4
            for (int j = 0; j < BKV; j++) {
                float p = __expf(Ss[tid * SS_STRIDE + j] - mx);
                Ss[tid * SS_STRIDE + j] = p;
                l += p;
            }
            rowM[tid] = mx; rowL[tid] = l; rowScale[tid] = sc;
        }
        __syncthreads();

        // PV accumulate
        {
            float sc = rowScale[r_pv];
            #pragma unroll
            for (int c = 0; c < 32; c++) acc[c] *= sc;
            for (int kk = 0; kk < BKV; kk++) {
                float p = Ss[r_pv * SS_STRIDE + kk];
                const float* vrow = &Vs[kk * HD + 4 * cg];
                #pragma unroll
                for (int c8 = 0; c8 < 8; c8++) {
                    float4 v4 = *(const float4*)(vrow + 16 * c8);
                    acc[c8 * 4 + 0] += p * v4.x;
                    acc[c8 * 4 + 1] += p * v4.y;
                    acc[c8 * 4 + 2] += p * v4.z;
                    acc[c8 * 4 + 3] += p * v4.w;
                }
            }
        }
    }

    // normalize + write
    float inv = 1.f / rowL[r_pv];
    float* op = O + (size_t)(qBase + r_pv) * DIM + head * HD + 4 * cg;
    #pragma unroll
    for (int c8 = 0; c8 < 8; c8++) {
        float4 v4 = make_float4(acc[c8 * 4 + 0] * inv, acc[c8 * 4 + 1] * inv,
                                acc[c8 * 4 + 2] * inv, acc[c8 * 4 + 3] * inv);
        *(float4*)(op + 16 * c8) = v4;
    }
}

// ---------------- launcher ----------------
extern "C" void kernel_launch(void* const* d_in, const int* in_sizes, int n_in,
                              void* d_out, int out_size)
{
    const float* x    = (const float*)d_in[0];
    const float* wq   = (const float*)d_in[1];
    const float* wk   = (const float*)d_in[2];
    const float* wv   = (const float*)d_in[3];
    const float* wo   = (const float*)d_in[4];
    const float* fcos = (const float*)d_in[5];
    const float* fsin = (const float*)d_in[6];
    // d_in[7] positions, d_in[8] mask: unused (causal mask applied analytically)
    float* out = (float*)d_out;

    float *qb, *kb, *vb, *ab;
    cudaGetSymbolAddress((void**)&qb, g_Q);
    cudaGetSymbolAddress((void**)&kb, g_K);
    cudaGetSymbolAddress((void**)&vb, g_V);
    cudaGetSymbolAddress((void**)&ab, g_A);

    // projections
    sgemm128<<<dim3(DIM / GBN,   S_LEN / GBM), 256>>>(x, wq, qb, S_LEN, DIM,   DIM);
    sgemm128<<<dim3(KVDIM / GBN, S_LEN / GBM), 256>>>(x, wk, kb, S_LEN, KVDIM, DIM);
    sgemm128<<<dim3(KVDIM / GBN, S_LEN / GBM), 256>>>(x, wv, vb, S_LEN, KVDIM, DIM);

    // RoPE on Q and K
    {
        int totQ = S_LEN * NH * (HD / 2);
        int totK = S_LEN * NKV * (HD / 2);
        rope_kernel<<<(totQ + 255) / 256, 256>>>(qb, fcos, fsin, NH);
        rope_kernel<<<(totK + 255) / 256, 256>>>(kb, fcos, fsin, NKV);
    }

    // attention
    cudaFuncSetAttribute(attn_kernel, cudaFuncAttributeMaxDynamicSharedMemorySize,
                         ATTN_SMEM_BYTES);
    attn_kernel<<<dim3(S_LEN / BQ, NH), 256, ATTN_SMEM_BYTES>>>(qb, kb, vb, ab);

    // output projection
    sgemm128<<<dim3(DIM / GBN, S_LEN / GBM), 256>>>(ab, wo, out, S_LEN, DIM, DIM);
}

// round 4
// speedup vs baseline: 1.3952x; 1.3952x over previous
#include <cuda_runtime.h>
#include <cuda_bf16.h>
#include <cstdint>

// ---------------- problem constants ----------------
#define S_LEN 2048
#define DIM   4096
#define NH    32
#define NKV   8
#define HD    128
#define KVDIM (NKV * HD)        // 1024
#define ATT_SCALE 0.08838834764831845f  // 128^-0.5

// ---------------- scratch (no allocations allowed) ----------------
__device__ float g_Q[S_LEN * DIM];     // 32 MB
__device__ float g_K[S_LEN * KVDIM];   //  8 MB
__device__ float g_V[S_LEN * KVDIM];   //  8 MB
__device__ float g_A[S_LEN * DIM];     // 32 MB (attention output, pre-Wo)

// ======================================================================
// TF32 tensor-core GEMM: C[M,N] = A[M,K] @ B[K,N], row-major.
// BM=128, BN=128, BK=16, 256 threads (8 warps, 4x2 warp grid, 32x64/warp).
// mma.sync.m16n8k8 tf32. PASSES=3 does hi/lo split (near-fp32 accuracy),
// PASSES=1 does plain tf32 (rel err ~4e-4).
// ======================================================================
#define TBM 128
#define TBN 128
#define TBK 16
#define SKA 20     // As row stride (floats): conflict-free frag reads, 16B-aligned stores
#define SNB 136    // Bs row stride (floats): conflict-free frag reads, 16B-aligned stores

__device__ __forceinline__ void tf32_split(float v, uint32_t& hi, uint32_t& lo) {
    uint32_t h;
    asm("cvt.rna.tf32.f32 %0, %1;" : "=r"(h) : "f"(v));
    hi = h;
    float r = v - __uint_as_float(h);
    asm("cvt.rna.tf32.f32 %0, %1;" : "=r"(lo) : "f"(r));
}
__device__ __forceinline__ uint32_t tf32_round(float v) {
    uint32_t h;
    asm("cvt.rna.tf32.f32 %0, %1;" : "=r"(h) : "f"(v));
    return h;
}
__device__ __forceinline__ void mma_tf32(float* c, const uint32_t* a, const uint32_t* b) {
    asm volatile("mma.sync.aligned.m16n8k8.row.col.f32.tf32.tf32.f32 "
        "{%0,%1,%2,%3}, {%4,%5,%6,%7}, {%8,%9}, {%0,%1,%2,%3};"
        : "+f"(c[0]), "+f"(c[1]), "+f"(c[2]), "+f"(c[3])
        : "r"(a[0]), "r"(a[1]), "r"(a[2]), "r"(a[3]), "r"(b[0]), "r"(b[1]));
}

template<int PASSES>
__global__ __launch_bounds__(256, 2) void tgemm(
    const float* __restrict__ A, const float* __restrict__ B,
    float* __restrict__ C, int M, int N, int K)
{
    __shared__ float As[TBM * SKA];   // [row][k]
    __shared__ float Bs[TBK * SNB];   // [k][n]

    const int tid  = threadIdx.x;
    const int lane = tid & 31;
    const int warp = tid >> 5;
    const int g    = lane >> 2;       // group id (row within 8)
    const int tig  = lane & 3;        // thread in group
    const int wRow = (warp >> 1) * 32;
    const int wCol = (warp & 1) * 64;
    const int rowBase0 = blockIdx.y * TBM;
    const int colBase0 = blockIdx.x * TBN;

    float acc[2][8][4];
    #pragma unroll
    for (int mi = 0; mi < 2; mi++)
        #pragma unroll
        for (int nj = 0; nj < 8; nj++)
            #pragma unroll
            for (int c = 0; c < 4; c++) acc[mi][nj][c] = 0.f;

    for (int k0 = 0; k0 < K; k0 += TBK) {
        // ---- stage tiles: 2 float4 of A, 2 float4 of B per thread ----
        #pragma unroll
        for (int p = 0; p < 2; p++) {
            int i = tid + p * 256;
            int ar = i >> 2, ac4 = (i & 3) * 4;
            float4 av = *(const float4*)(A + (size_t)(rowBase0 + ar) * K + k0 + ac4);
            *(float4*)&As[ar * SKA + ac4] = av;
            int br = i >> 5, bc4 = (i & 31) * 4;
            float4 bv = *(const float4*)(B + (size_t)(k0 + br) * N + colBase0 + bc4);
            *(float4*)&Bs[br * SNB + bc4] = bv;
        }
        __syncthreads();

        #pragma unroll
        for (int ks = 0; ks < 2; ks++) {
            const int kb = ks * 8;
            // A fragments (hi/lo)
            uint32_t ahi[2][4], alo[2][4];
            #pragma unroll
            for (int mi = 0; mi < 2; mi++) {
                const int r0 = wRow + mi * 16;
                float v0 = As[(r0 + g)     * SKA + kb + tig];
                float v1 = As[(r0 + g + 8) * SKA + kb + tig];
                float v2 = As[(r0 + g)     * SKA + kb + tig + 4];
                float v3 = As[(r0 + g + 8) * SKA + kb + tig + 4];
                if (PASSES == 3) {
                    tf32_split(v0, ahi[mi][0], alo[mi][0]);
                    tf32_split(v1, ahi[mi][1], alo[mi][1]);
                    tf32_split(v2, ahi[mi][2], alo[mi][2]);
                    tf32_split(v3, ahi[mi][3], alo[mi][3]);
                } else {
                    ahi[mi][0] = tf32_round(v0);
                    ahi[mi][1] = tf32_round(v1);
                    ahi[mi][2] = tf32_round(v2);
                    ahi[mi][3] = tf32_round(v3);
                }
            }
            #pragma unroll
            for (int nj = 0; nj < 8; nj++) {
                const int cc = wCol + nj * 8 + g;
                float b0 = Bs[(kb + tig)     * SNB + cc];
                float b1 = Bs[(kb + tig + 4) * SNB + cc];
                uint32_t bh[2], bl[2];
                if (PASSES == 3) {
                    tf32_split(b0, bh[0], bl[0]);
                    tf32_split(b1, bh[1], bl[1]);
                } else {
                    bh[0] = tf32_round(b0);
                    bh[1] = tf32_round(b1);
                }
                #pragma unroll
                for (int mi = 0; mi < 2; mi++) {
                    if (PASSES == 3) {
                        mma_tf32(acc[mi][nj], alo[mi], bh);
                        mma_tf32(acc[mi][nj], ahi[mi], bl);
                    }
                    mma_tf32(acc[mi][nj], ahi[mi], bh);
                }
            }
        }
        __syncthreads();
    }

    // ---- writeback (float2 per row-half per mma tile) ----
    #pragma unroll
    for (int mi = 0; mi < 2; mi++) {
        #pragma unroll
        for (int nj = 0; nj < 8; nj++) {
            int row = rowBase0 + wRow + mi * 16 + g;
            int col = colBase0 + wCol + nj * 8 + tig * 2;
            *(float2*)&C[(size_t)row * N + col] =
                make_float2(acc[mi][nj][0], acc[mi][nj][1]);
            *(float2*)&C[(size_t)(row + 8) * N + col] =
                make_float2(acc[mi][nj][2], acc[mi][nj][3]);
        }
    }
}

// ---------------- RoPE (interleaved pairs, matches reference) ----------------
__global__ void rope_kernel(float* __restrict__ t,
                            const float* __restrict__ cosb,
                            const float* __restrict__ sinb,
                            int nheads)
{
    int idx = blockIdx.x * blockDim.x + threadIdx.x;
    int total = S_LEN * nheads * (HD / 2);
    if (idx >= total) return;
    int i = idx & 63;                 // pair index 0..63
    int h = (idx >> 6) % nheads;
    int s = idx / (64 * nheads);
    float c  = cosb[s * 64 + i];
    float sn = sinb[s * 64 + i];
    float* p = t + (size_t)s * (nheads * HD) + h * HD + 2 * i;
    float t0 = p[0], t1 = p[1];
    p[0] = t0 * c - t1 * sn;
    p[1] = t0 * sn + t1 * c;
}

// ---------------- Flash-style causal attention (fp32 SIMT) ----------------
#define BQ  64
#define BKV 64
#define KS_STRIDE 129
#define SS_STRIDE 65

#define ATTN_SMEM_FLOATS (64*128 + 64*KS_STRIDE + 64*128 + 64*SS_STRIDE + 192)
#define ATTN_SMEM_BYTES  (ATTN_SMEM_FLOATS * 4)

__global__ __launch_bounds__(256, 2) void attn_kernel(
    const float* __restrict__ Q, const float* __restrict__ K,
    const float* __restrict__ V, float* __restrict__ O)
{
    extern __shared__ float sm[];
    float* Qs = sm;                        // [64][128]
    float* Ks = Qs + 64 * 128;             // [64][129]
    float* Vs = Ks + 64 * KS_STRIDE;       // [64][128]
    float* Ss = Vs + 64 * 128;             // [64][65]
    float* rowM = Ss + 64 * SS_STRIDE;
    float* rowL = rowM + 64;
    float* rowScale = rowL + 64;

    const int tid  = threadIdx.x;
    const int qt   = blockIdx.x;
    const int head = blockIdx.y;
    const int kvh  = head >> 2;            // REPEATS = 4
    const int qBase = qt * BQ;

    for (int i = tid; i < BQ * (HD / 4); i += 256) {
        int r = i >> 5, c4 = (i & 31) << 2;
        *(float4*)&Qs[r * HD + c4] =
            *(const float4*)(Q + (size_t)(qBase + r) * DIM + head * HD + c4);
    }
    if (tid < 64) { rowM[tid] = -1e30f; rowL[tid] = 0.f; }

    float acc[32];
    #pragma unroll
    for (int i = 0; i < 32; i++) acc[i] = 0.f;

    const int r_pv = tid >> 2;
    const int cg   = tid & 3;
    const int ty = tid >> 4;
    const int tx = tid & 15;

    const int nkb = qt + 1;
    for (int kb = 0; kb < nkb; kb++) {
        const int kvStart = kb * BKV;
        __syncthreads();

        for (int i = tid; i < BKV * (HD / 4); i += 256) {
            int r = i >> 5, c4 = (i & 31) << 2;
            float4 k4 = *(const float4*)(K + (size_t)(kvStart + r) * KVDIM + kvh * HD + c4);
            Ks[r * KS_STRIDE + c4 + 0] = k4.x;
            Ks[r * KS_STRIDE + c4 + 1] = k4.y;
            Ks[r * KS_STRIDE + c4 + 2] = k4.z;
            Ks[r * KS_STRIDE + c4 + 3] = k4.w;
            *(float4*)&Vs[r * HD + c4] =
                *(const float4*)(V + (size_t)(kvStart + r) * KVDIM + kvh * HD + c4);
        }
        __syncthreads();

        float s4[4][4];
        #pragma unroll
        for (int i = 0; i < 4; i++)
            #pragma unroll
            for (int j = 0; j < 4; j++) s4[i][j] = 0.f;

        for (int d = 0; d < HD; d++) {
            float qv[4], kv[4];
            #pragma unroll
            for (int i = 0; i < 4; i++) qv[i] = Qs[(ty * 4 + i) * HD + d];
            #pragma unroll
            for (int j = 0; j < 4; j++) kv[j] = Ks[(tx + 16 * j) * KS_STRIDE + d];
            #pragma unroll
            for (int i = 0; i < 4; i++)
                #pragma unroll
                for (int j = 0; j < 4; j++)
                    s4[i][j] += qv[i] * kv[j];
        }
        #pragma unroll
        for (int i = 0; i < 4; i++) {
            int qpos = qBase + ty * 4 + i;
            #pragma unroll
            for (int j = 0; j < 4; j++) {
                int kpos = kvStart + tx + 16 * j;
                float v = s4[i][j] * ATT_SCALE;
                if (kpos > qpos) v = -1e9f;
                Ss[(ty * 4 + i) * SS_STRIDE + tx + 16 * j] = v;
            }
        }
        __syncthreads();

        if (tid < 64) {
            float m = rowM[tid];
            float mx = m;
            #pragma unroll 8
            for (int j = 0; j < BKV; j++) mx = fmaxf(mx, Ss[tid * SS_STRIDE + j]);
            float sc = __expf(m - mx);
            float l = rowL[tid] * sc;
            #pragma unroll 4
            for (int j = 0; j < BKV; j++) {
                float p = __expf(Ss[tid * SS_STRIDE + j] - mx);
                Ss[tid * SS_STRIDE + j] = p;
                l += p;
            }
            rowM[tid] = mx; rowL[tid] = l; rowScale[tid] = sc;
        }
        __syncthreads();

        {
            float sc = rowScale[r_pv];
            #pragma unroll
            for (int c = 0; c < 32; c++) acc[c] *= sc;
            for (int kk = 0; kk < BKV; kk++) {
                float p = Ss[r_pv * SS_STRIDE + kk];
                const float* vrow = &Vs[kk * HD + 4 * cg];
                #pragma unroll
                for (int c8 = 0; c8 < 8; c8++) {
                    float4 v4 = *(const float4*)(vrow + 16 * c8);
                    acc[c8 * 4 + 0] += p * v4.x;
                    acc[c8 * 4 + 1] += p * v4.y;
                    acc[c8 * 4 + 2] += p * v4.z;
                    acc[c8 * 4 + 3] += p * v4.w;
                }
            }
        }
    }

    float inv = 1.f / rowL[r_pv];
    float* op = O + (size_t)(qBase + r_pv) * DIM + head * HD + 4 * cg;
    #pragma unroll
    for (int c8 = 0; c8 < 8; c8++) {
        float4 v4 = make_float4(acc[c8 * 4 + 0] * inv, acc[c8 * 4 + 1] * inv,
                                acc[c8 * 4 + 2] * inv, acc[c8 * 4 + 3] * inv);
        *(float4*)(op + 16 * c8) = v4;
    }
}

// ---------------- launcher ----------------
extern "C" void kernel_launch(void* const* d_in, const int* in_sizes, int n_in,
                              void* d_out, int out_size)
{
    const float* x    = (const float*)d_in[0];
    const float* wq   = (const float*)d_in[1];
    const float* wk   = (const float*)d_in[2];
    const float* wv   = (const float*)d_in[3];
    const float* wo   = (const float*)d_in[4];
    const float* fcos = (const float*)d_in[5];
    const float* fsin = (const float*)d_in[6];
    float* out = (float*)d_out;

    float *qb, *kb, *vb, *ab;
    cudaGetSymbolAddress((void**)&qb, g_Q);
    cudaGetSymbolAddress((void**)&kb, g_K);
    cudaGetSymbolAddress((void**)&vb, g_V);
    cudaGetSymbolAddress((void**)&ab, g_A);

    // projections: 3xTF32 (near-fp32) for Q,K,V — errors there get amplified
    // through the softmax logits; plain TF32 would risk the 1e-3 bound.
    tgemm<3><<<dim3(DIM / TBN,   S_LEN / TBM), 256>>>(x, wq, qb, S_LEN, DIM,   DIM);
    tgemm<3><<<dim3(KVDIM / TBN, S_LEN / TBM), 256>>>(x, wk, kb, S_LEN, KVDIM, DIM);
    tgemm<3><<<dim3(KVDIM / TBN, S_LEN / TBM), 256>>>(x, wv, vb, S_LEN, KVDIM, DIM);

    // RoPE on Q and K
    {
        int totQ = S_LEN * NH * (HD / 2);
        int totK = S_LEN * NKV * (HD / 2);
        rope_kernel<<<(totQ + 255) / 256, 256>>>(qb, fcos, fsin, NH);
        rope_kernel<<<(totK + 255) / 256, 256>>>(kb, fcos, fsin, NKV);
    }

    // attention (fp32 SIMT flash)
    cudaFuncSetAttribute(attn_kernel, cudaFuncAttributeMaxDynamicSharedMemorySize,
                         ATTN_SMEM_BYTES);
    attn_kernel<<<dim3(S_LEN / BQ, NH), 256, ATTN_SMEM_BYTES>>>(qb, kb, vb, ab);

    // output projection: single-pass TF32 (err ~4e-4, lands directly on output)
    tgemm<1><<<dim3(DIM / TBN, S_LEN / TBM), 256>>>(ab, wo, out, S_LEN, DIM, DIM);
}